// round 15
// baseline (speedup 1.0000x reference)
#include <cuda_runtime.h>
#include <cuda_fp16.h>

// Problem constants (fixed shapes from reference)
#define B_   2
#define T_   32
#define C_   128
#define G_   4
#define CPG  32      // channels per head-group = C/G
#define H_   64
#define W_   64
#define HC_  16      // coarse h
#define WC_  16      // coarse w
#define TQ   8       // q-chunk per block
#define HW_  (H_*W_)     // 4096
#define CHW_ (C_*HW_)    // 524288

typedef unsigned long long u64t;

// out[b,q,g*CPG+c,h,w] = sum_k A_fine[g,b,q,k,h,w] * x[b,k,g*CPG+c,h,w]
// A_fine = bilinear upsample (x4, half-pixel centers, edge clamp) of attn.
// R12 structure (512-thr block covers all 64 w: phase-1 amortized over both
// w-halves -> lowest wavefront count) + R14 streaming L1 prefetch of x at
// k+8 (converts mainloop LDG L2-waits into L1 hits). q8c4 FFMA2, fp16 A.

__device__ __forceinline__ void ffma2(u64t& d, u64t a, u64t b) {
    asm("fma.rn.f32x2 %0, %1, %2, %0;" : "+l"(d) : "l"(a), "l"(b));
}
__device__ __forceinline__ u64t bcast2(float x) {
    u64t d;
    asm("mov.b64 %0, {%1, %1};" : "=l"(d) : "f"(x));
    return d;
}
__device__ __forceinline__ u64t pack2(float lo, float hi) {
    u64t d;
    asm("mov.b64 %0, {%1, %2};" : "=l"(d) : "f"(lo), "f"(hi));
    return d;
}
__device__ __forceinline__ void unpack2(float& lo, float& hi, u64t v) {
    asm("mov.b64 {%0, %1}, %2;" : "=f"(lo), "=f"(hi) : "l"(v));
}
__device__ __forceinline__ void pf_l1(const float* p) {
    asm volatile("prefetch.global.L1 [%0];" :: "l"(p));
}

__global__ __launch_bounds__(512, 2) void temporal_agg_kernel(
    const float* __restrict__ x,
    const float* __restrict__ attn,
    float* __restrict__ out)
{
    __shared__ float   Cy[TQ * T_ * WC_];          // [q*32+k][wc]        16 KB
    __shared__ __half2 A2h[T_ * 4 * W_];           // [k][qpair][w64]     32 KB

    const int qc  = blockIdx.x;          // 0..3  (q-chunk)  -- fastest: L2 reuse of x
    const int zz  = blockIdx.y;          // (b*G+g)*H + h
    const int h   = zz & (H_ - 1);
    const int bg  = zz >> 6;
    const int g   = bg & (G_ - 1);
    const int b   = bg >> 2;

    const int tid  = threadIdx.x;        // 0..511
    const int wl   = tid & 31;
    const int warp = tid >> 5;           // 0..15

    // ---- y interpolation coefficients for this fine row h ----
    // src_y = (h + 0.5)/4 - 0.5 = h*0.25 - 0.375 ; edge clamp
    float fy  = h * 0.25f - 0.375f;
    float fyf = floorf(fy);
    float wy1 = fy - fyf;
    int   h0  = (int)fyf;
    int   h1  = min(h0 + 1, HC_ - 1);
    h0 = max(h0, 0);

    // ---- phase 1a: Cy[q*32+k][wc] = lerp_y(coarse), once for both w-halves ----
    // coarse attn layout: ((((g*B+b)*T + q)*T + k)*HC + hc)*WC + wc
    const float* cb = attn + ((((size_t)g * B_ + b) * T_ + (size_t)qc * TQ) * T_) * (HC_ * WC_);
    #pragma unroll
    for (int i = 0; i < (TQ * T_ * WC_) / 512; ++i) {    // 8 iters
        int idx = i * 512 + tid;
        int wc  = idx & (WC_ - 1);
        int qk  = idx >> 4;               // q*32 + k
        const float* p = cb + qk * (HC_ * WC_) + wc;
        float v0 = p[h0 * WC_];
        float v1 = p[h1 * WC_];
        Cy[idx] = fmaf(wy1, v1 - v0, v0);
    }
    __syncthreads();

    // ---- phase 1b: x-lerp + transpose -> A2h[k][qp][wf] (half2 q-pairs) ----
    // warp -> (k-slice kh = warp>>1, w-half wh = warp&1); thread covers wf.
    {
        const int wh  = warp & 1;
        const int kh  = warp >> 1;                // 0..7
        const int wf  = wh * 32 + wl;
        float fx  = wf * 0.25f - 0.375f;
        float fxf = floorf(fx);
        float wx1 = fx - fxf;
        int   w0  = (int)fxf;
        int   w1  = min(w0 + 1, WC_ - 1);
        w0 = max(w0, 0);
        #pragma unroll
        for (int i = 0; i < 4; ++i) {
            int k = kh + 8 * i;                   // 0..31
            float a[TQ];
            #pragma unroll
            for (int q = 0; q < TQ; ++q) {
                float v0 = Cy[(q * T_ + k) * WC_ + w0];
                float v1 = Cy[(q * T_ + k) * WC_ + w1];
                a[q] = fmaf(wx1, v1 - v0, v0);
            }
            #pragma unroll
            for (int qp = 0; qp < 4; ++qp)
                A2h[(k * 4 + qp) * W_ + wf] =
                    __floats2half2_rn(a[2 * qp], a[2 * qp + 1]);
        }
    }
    __syncthreads();

    // ---- phase 2: per-pixel GEMM slice, f32x2 over q-pairs ----
    // warp -> (w-half = warp>>3, channel group cg = warp&7) -> 4 channels each
    const int wchm = warp >> 3;
    const int cg   = warp & 7;
    const int wf   = wchm * 32 + wl;
    const int cbase = g * CPG + cg * 4;

    const float* xp = x + ((size_t)b * T_ * C_ + cbase) * HW_ + h * W_ + wf;
    const __half2* ahp = A2h + wf;

    u64t acc[4][4];                     // [qpair][c]
    #pragma unroll
    for (int qp = 0; qp < 4; ++qp)
        #pragma unroll
        for (int c = 0; c < 4; ++c)
            acc[qp][c] = 0ull;

    // warm the prefetch pipeline for k = 0..7 (one line per k; rest in-loop)
    #pragma unroll
    for (int k = 0; k < 8; ++k)
        pf_l1(xp + k * CHW_);

    #pragma unroll 4
    for (int k = 0; k < T_; ++k) {
        const float* xk = xp + k * CHW_;          // 32-bit offset arithmetic
        // streaming prefetch: 4 c-lines of k+8 (~2 unroll groups ahead)
        if (k < T_ - 8) {
            const float* pf = xk + 8 * CHW_;
            pf_l1(pf);
            pf_l1(pf + HW_);
            pf_l1(pf + 2 * HW_);
            pf_l1(pf + 3 * HW_);
        }
        u64t xv[4];
        #pragma unroll
        for (int c = 0; c < 4; ++c)
            xv[c] = bcast2(xk[c * HW_]);
        u64t av[4];
        #pragma unroll
        for (int qp = 0; qp < 4; ++qp) {
            float2 f = __half22float2(ahp[(k * 4 + qp) * W_]);
            av[qp] = pack2(f.x, f.y);
        }
        #pragma unroll
        for (int qp = 0; qp < 4; ++qp)
            #pragma unroll
            for (int c = 0; c < 4; ++c)
                ffma2(acc[qp][c], av[qp], xv[c]);
    }

    // ---- store: out[(((b*T+q)*C + c)*H + h)*W + w], q = 2*qp + {0,1} ----
    float* ob = out + (((size_t)b * T_ + (size_t)qc * TQ) * C_ + cbase) * HW_ + h * W_ + wf;
    #pragma unroll
    for (int qp = 0; qp < 4; ++qp) {
        #pragma unroll
        for (int c = 0; c < 4; ++c) {
            float lo, hi;
            unpack2(lo, hi, acc[qp][c]);
            ob[(2 * qp) * CHW_ + c * HW_]     = lo;
            ob[(2 * qp + 1) * CHW_ + c * HW_] = hi;
        }
    }
}

extern "C" void kernel_launch(void* const* d_in, const int* in_sizes, int n_in,
                              void* d_out, int out_size)
{
    const float* x    = (const float*)d_in[0];   // (2,32,128,64,64)
    const float* attn = (const float*)d_in[1];   // (4,2,32,32,16,16)
    float* out        = (float*)d_out;           // (2,32,128,64,64)

    dim3 grid(T_ / TQ /*4 q-chunks*/, B_ * G_ * H_ /*512*/);
    temporal_agg_kernel<<<grid, 512>>>(x, attn, out);
}

// round 16
// speedup vs baseline: 1.0173x; 1.0173x over previous
#include <cuda_runtime.h>
#include <cuda_fp16.h>

// Problem constants (fixed shapes from reference)
#define B_   2
#define T_   32
#define C_   128
#define G_   4
#define CPG  32      // channels per head-group = C/G
#define H_   64
#define W_   64
#define HC_  16      // coarse h
#define WC_  16      // coarse w
#define TQ   8       // q-chunk per block
#define HW_  (H_*W_)     // 4096
#define CHW_ (C_*HW_)    // 524288

typedef unsigned long long u64t;

// out[b,q,g*CPG+c,h,w] = sum_k A_fine[g,b,q,k,h,w] * x[b,k,g*CPG+c,h,w]
// A_fine = bilinear upsample (x4, half-pixel centers, edge clamp) of attn.
// Champion (R14) + issue/ALU trims:
//  - A tile as one LDS.128 per k: layout [k][wl][qp0..3], 16B lane slots
//  - dual strided pointers so loads AND k+8 prefetches use immediate offsets
//  - full 4-line prefetch warm-up for k<8

__device__ __forceinline__ void ffma2(u64t& d, u64t a, u64t b) {
    asm("fma.rn.f32x2 %0, %1, %2, %0;" : "+l"(d) : "l"(a), "l"(b));
}
__device__ __forceinline__ u64t bcast2(float x) {
    u64t d;
    asm("mov.b64 %0, {%1, %1};" : "=l"(d) : "f"(x));
    return d;
}
__device__ __forceinline__ u64t pack2(float lo, float hi) {
    u64t d;
    asm("mov.b64 %0, {%1, %2};" : "=l"(d) : "f"(lo), "f"(hi));
    return d;
}
__device__ __forceinline__ void unpack2(float& lo, float& hi, u64t v) {
    asm("mov.b64 {%0, %1}, %2;" : "=f"(lo), "=f"(hi) : "l"(v));
}
__device__ __forceinline__ void pf_l1(const float* p) {
    asm volatile("prefetch.global.L1 [%0];" :: "l"(p));
}

__global__ __launch_bounds__(256, 4) void temporal_agg_kernel(
    const float* __restrict__ x,
    const float* __restrict__ attn,
    float* __restrict__ out)
{
    __shared__ float Cy[TQ * T_ * WC_];                 // [q*32+k][wc]     16 KB
    __shared__ __align__(16) __half2 A2h[T_ * 32 * 4];  // [k][wl][qp0..3]  16 KB

    const int qc  = blockIdx.x;          // 0..3  (q-chunk)  -- fastest: L2 reuse of x
    const int wch = blockIdx.y;          // 0..1  (w-chunk of 32)
    const int zz  = blockIdx.z;          // (b*G+g)*H + h
    const int h   = zz & (H_ - 1);
    const int bg  = zz >> 6;
    const int g   = bg & (G_ - 1);
    const int b   = bg >> 2;

    const int tid = threadIdx.x;         // 0..255
    const int wl  = tid & 31;

    // ---- y interpolation coefficients for this fine row h ----
    // src_y = (h + 0.5)/4 - 0.5 = h*0.25 - 0.375 ; edge clamp
    float fy  = h * 0.25f - 0.375f;
    float fyf = floorf(fy);
    float wy1 = fy - fyf;
    int   h0  = (int)fyf;
    int   h1  = min(h0 + 1, HC_ - 1);
    h0 = max(h0, 0);

    // ---- phase 1a: Cy[q*32+k][wc] = lerp_y(coarse) ----
    // coarse attn layout: ((((g*B+b)*T + q)*T + k)*HC + hc)*WC + wc
    const float* cb = attn + ((((size_t)g * B_ + b) * T_ + (size_t)qc * TQ) * T_) * (HC_ * WC_);
    #pragma unroll
    for (int i = 0; i < (TQ * T_ * WC_) / 256; ++i) {    // 16 iters
        int idx = i * 256 + tid;
        int wc  = idx & (WC_ - 1);
        int qk  = idx >> 4;               // q*32 + k
        const float* p = cb + qk * (HC_ * WC_) + wc;
        float v0 = p[h0 * WC_];
        float v1 = p[h1 * WC_];
        Cy[idx] = fmaf(wy1, v1 - v0, v0);
    }
    __syncthreads();

    // ---- phase 1b: x-lerp + transpose into A2h[k][wl][qp0..3] ----
    {
        const int wf = wch * 32 + wl;
        float fx  = wf * 0.25f - 0.375f;
        float fxf = floorf(fx);
        float wx1 = fx - fxf;
        int   w0  = (int)fxf;
        int   w1  = min(w0 + 1, WC_ - 1);
        w0 = max(w0, 0);
        const int kb = tid >> 5;                  // 0..7
        #pragma unroll
        for (int i = 0; i < 4; ++i) {
            int k = kb + 8 * i;                   // 0..31
            float a[TQ];
            #pragma unroll
            for (int q = 0; q < TQ; ++q) {
                float v0 = Cy[(q * T_ + k) * WC_ + w0];
                float v1 = Cy[(q * T_ + k) * WC_ + w1];
                a[q] = fmaf(wx1, v1 - v0, v0);
            }
            __half2 hp[4];
            #pragma unroll
            for (int qp = 0; qp < 4; ++qp)
                hp[qp] = __floats2half2_rn(a[2 * qp], a[2 * qp + 1]);
            *(uint4*)&A2h[(k * 32 + wl) * 4] =
                make_uint4(*(unsigned*)&hp[0], *(unsigned*)&hp[1],
                           *(unsigned*)&hp[2], *(unsigned*)&hp[3]);
        }
    }
    __syncthreads();

    // ---- phase 2: per-pixel GEMM slice, f32x2 over q-pairs ----
    // thread: w lane (32), channel group cg (8 warps) -> 4 channels each
    const int cg = tid >> 5;
    const int wf = wch * 32 + wl;
    const int cbase = g * CPG + cg * 4;

    const float* xp = x + ((size_t)b * T_ * C_ + cbase) * HW_ + h * W_ + wf;
    const uint4* a4 = (const uint4*)A2h + wl;       // + k*32 per k (16B slots)

    u64t acc[4][4];                     // [qpair][c]
    #pragma unroll
    for (int qp = 0; qp < 4; ++qp)
        #pragma unroll
        for (int c = 0; c < 4; ++c)
            acc[qp][c] = 0ull;

    // full prefetch warm-up: 4 c-lines for k = 0..7
    #pragma unroll
    for (int k = 0; k < 8; ++k) {
        const float* pf = xp + k * CHW_;
        pf_l1(pf);
        pf_l1(pf + HW_);
        pf_l1(pf + 2 * HW_);
        pf_l1(pf + 3 * HW_);
    }

    // dual strided pointers: xk for loads, pfk = xk + 8*CHW for prefetch.
    // Both advance by CHW per k so all accesses use small immediate offsets.
    const float* xk  = xp;
    const float* pfk = xp + 8 * CHW_;
    #pragma unroll 4
    for (int k = 0; k < T_; ++k) {
        if (k < T_ - 8) {
            pf_l1(pfk);
            pf_l1(pfk + HW_);
            pf_l1(pfk + 2 * HW_);
            pf_l1(pfk + 3 * HW_);
        }
        u64t xv[4];
        #pragma unroll
        for (int c = 0; c < 4; ++c)
            xv[c] = bcast2(xk[c * HW_]);
        uint4 araw = a4[k * 32];                   // one LDS.128: 4 q-pair half2
        const __half2* ah = (const __half2*)&araw;
        u64t av[4];
        #pragma unroll
        for (int qp = 0; qp < 4; ++qp) {
            float2 f = __half22float2(ah[qp]);
            av[qp] = pack2(f.x, f.y);
        }
        #pragma unroll
        for (int qp = 0; qp < 4; ++qp)
            #pragma unroll
            for (int c = 0; c < 4; ++c)
                ffma2(acc[qp][c], av[qp], xv[c]);
        xk  += CHW_;
        pfk += CHW_;
    }

    // ---- store: out[(((b*T+q)*C + c)*H + h)*W + w], q = 2*qp + {0,1} ----
    float* ob = out + (((size_t)b * T_ + (size_t)qc * TQ) * C_ + cbase) * HW_ + h * W_ + wf;
    #pragma unroll
    for (int qp = 0; qp < 4; ++qp) {
        #pragma unroll
        for (int c = 0; c < 4; ++c) {
            float lo, hi;
            unpack2(lo, hi, acc[qp][c]);
            ob[(2 * qp) * CHW_ + c * HW_]     = lo;
            ob[(2 * qp + 1) * CHW_ + c * HW_] = hi;
        }
    }
}

extern "C" void kernel_launch(void* const* d_in, const int* in_sizes, int n_in,
                              void* d_out, int out_size)
{
    const float* x    = (const float*)d_in[0];   // (2,32,128,64,64)
    const float* attn = (const float*)d_in[1];   // (4,2,32,32,16,16)
    float* out        = (float*)d_out;           // (2,32,128,64,64)

    dim3 grid(T_ / TQ /*4 q-chunks*/, W_ / 32 /*2 w-chunks*/, B_ * G_ * H_ /*512*/);
    temporal_agg_kernel<<<grid, 256>>>(x, attn, out);
}

// round 17
// speedup vs baseline: 1.0454x; 1.0277x over previous
#include <cuda_runtime.h>
#include <cuda_fp16.h>

// Problem constants (fixed shapes from reference)
#define B_   2
#define T_   32
#define C_   128
#define G_   4
#define CPG  32      // channels per head-group = C/G
#define H_   64
#define W_   64
#define HC_  16      // coarse h
#define WC_  16      // coarse w
#define TQ   8       // q-chunk per block
#define HW_  (H_*W_)     // 4096
#define CHW_ (C_*HW_)    // 524288

typedef unsigned long long u64t;

// out[b,q,g*CPG+c,h,w] = sum_k A_fine[g,b,q,k,h,w] * x[b,k,g*CPG+c,h,w]
// A_fine = bilinear upsample (x4, half-pixel centers, edge clamp) of attn.
// Champion (R14): q8c4 FFMA2, A as half2 q-pairs [k][qp][wl] (4x LDS.32,
// conflict-free), streaming L1 prefetch at k+8.
// This round: group-strided base pointers (xk / pfk / ahk advanced once per
// 4-k group) so every per-k access is a small immediate -> kills the
// IADD3.X chains that put alu at 16% (pf offsets were >8MB imm window).

__device__ __forceinline__ void ffma2(u64t& d, u64t a, u64t b) {
    asm("fma.rn.f32x2 %0, %1, %2, %0;" : "+l"(d) : "l"(a), "l"(b));
}
__device__ __forceinline__ u64t bcast2(float x) {
    u64t d;
    asm("mov.b64 %0, {%1, %1};" : "=l"(d) : "f"(x));
    return d;
}
__device__ __forceinline__ u64t pack2(float lo, float hi) {
    u64t d;
    asm("mov.b64 %0, {%1, %2};" : "=l"(d) : "f"(lo), "f"(hi));
    return d;
}
__device__ __forceinline__ void unpack2(float& lo, float& hi, u64t v) {
    asm("mov.b64 {%0, %1}, %2;" : "=f"(lo), "=f"(hi) : "l"(v));
}
__device__ __forceinline__ void pf_l1(const float* p) {
    asm volatile("prefetch.global.L1 [%0];" :: "l"(p));
}

__global__ __launch_bounds__(256, 4) void temporal_agg_kernel(
    const float* __restrict__ x,
    const float* __restrict__ attn,
    float* __restrict__ out)
{
    __shared__ float   Cy[TQ * T_ * WC_];          // [q*32+k][wc]        16 KB
    __shared__ __half2 A2h[T_ * 4 * 32];           // [k][qpair][wl]      16 KB

    const int qc  = blockIdx.x;          // 0..3  (q-chunk)  -- fastest: L2 reuse of x
    const int wch = blockIdx.y;          // 0..1  (w-chunk of 32)
    const int zz  = blockIdx.z;          // (b*G+g)*H + h
    const int h   = zz & (H_ - 1);
    const int bg  = zz >> 6;
    const int g   = bg & (G_ - 1);
    const int b   = bg >> 2;

    const int tid = threadIdx.x;         // 0..255
    const int wl  = tid & 31;

    // ---- y interpolation coefficients for this fine row h ----
    // src_y = (h + 0.5)/4 - 0.5 = h*0.25 - 0.375 ; edge clamp
    float fy  = h * 0.25f - 0.375f;
    float fyf = floorf(fy);
    float wy1 = fy - fyf;
    int   h0  = (int)fyf;
    int   h1  = min(h0 + 1, HC_ - 1);
    h0 = max(h0, 0);

    // ---- phase 1a: Cy[q*32+k][wc] = lerp_y(coarse) ----
    // coarse attn layout: ((((g*B+b)*T + q)*T + k)*HC + hc)*WC + wc
    const float* cb = attn + ((((size_t)g * B_ + b) * T_ + (size_t)qc * TQ) * T_) * (HC_ * WC_);
    #pragma unroll
    for (int i = 0; i < (TQ * T_ * WC_) / 256; ++i) {    // 16 iters
        int idx = i * 256 + tid;
        int wc  = idx & (WC_ - 1);
        int qk  = idx >> 4;               // q*32 + k
        const float* p = cb + qk * (HC_ * WC_) + wc;
        float v0 = p[h0 * WC_];
        float v1 = p[h1 * WC_];
        Cy[idx] = fmaf(wy1, v1 - v0, v0);
    }
    __syncthreads();

    // ---- phase 1b: x-lerp + transpose into q-pair half2 A2h[k][qp][wl] ----
    {
        const int wf = wch * 32 + wl;
        float fx  = wf * 0.25f - 0.375f;
        float fxf = floorf(fx);
        float wx1 = fx - fxf;
        int   w0  = (int)fxf;
        int   w1  = min(w0 + 1, WC_ - 1);
        w0 = max(w0, 0);
        const int kb = tid >> 5;                  // 0..7
        #pragma unroll
        for (int i = 0; i < 4; ++i) {
            int k = kb + 8 * i;                   // 0..31
            float a[TQ];
            #pragma unroll
            for (int q = 0; q < TQ; ++q) {
                float v0 = Cy[(q * T_ + k) * WC_ + w0];
                float v1 = Cy[(q * T_ + k) * WC_ + w1];
                a[q] = fmaf(wx1, v1 - v0, v0);
            }
            #pragma unroll
            for (int qp = 0; qp < 4; ++qp)
                A2h[(k * 4 + qp) * 32 + wl] =
                    __floats2half2_rn(a[2 * qp], a[2 * qp + 1]);
        }
    }
    __syncthreads();

    // ---- phase 2: per-pixel GEMM slice, f32x2 over q-pairs ----
    // thread: w lane (32), channel group cg (8 warps) -> 4 channels each
    const int cg = tid >> 5;
    const int wf = wch * 32 + wl;
    const int cbase = g * CPG + cg * 4;

    const float* xp = x + ((size_t)b * T_ * C_ + cbase) * HW_ + h * W_ + wf;

    u64t acc[4][4];                     // [qpair][c]
    #pragma unroll
    for (int qp = 0; qp < 4; ++qp)
        #pragma unroll
        for (int c = 0; c < 4; ++c)
            acc[qp][c] = 0ull;

    // warm the prefetch pipeline for k = 0..7 (one line per k, as in R14)
    #pragma unroll
    for (int k = 0; k < 8; ++k)
        pf_l1(xp + k * CHW_);

    // group-strided pointers: advance once per 4-k group; all inner accesses
    // are compile-time immediates (max ~6.3MB, inside the imm window).
    const float*   xk  = xp;                      // loads base
    const float*   pfk = xp + 8 * CHW_;           // prefetch base (k+8)
    const __half2* ahk = A2h + wl;                // A base

    for (int kg = 0; kg < 8; ++kg) {
        #pragma unroll
        for (int kk = 0; kk < 4; ++kk) {
            if (kg < 6) {                         // prefetch k+8 for k < 24
                const float* pf = pfk + kk * CHW_;
                pf_l1(pf);
                pf_l1(pf + HW_);
                pf_l1(pf + 2 * HW_);
                pf_l1(pf + 3 * HW_);
            }
            u64t xv[4];
            #pragma unroll
            for (int c = 0; c < 4; ++c)
                xv[c] = bcast2(xk[kk * CHW_ + c * HW_]);
            u64t av[4];
            #pragma unroll
            for (int qp = 0; qp < 4; ++qp) {
                float2 f = __half22float2(ahk[(kk * 4 + qp) * 32]);
                av[qp] = pack2(f.x, f.y);
            }
            #pragma unroll
            for (int qp = 0; qp < 4; ++qp)
                #pragma unroll
                for (int c = 0; c < 4; ++c)
                    ffma2(acc[qp][c], av[qp], xv[c]);
        }
        xk  += 4 * CHW_;
        pfk += 4 * CHW_;
        ahk += 4 * 4 * 32;
    }

    // ---- store: out[(((b*T+q)*C + c)*H + h)*W + w], q = 2*qp + {0,1} ----
    float* ob = out + (((size_t)b * T_ + (size_t)qc * TQ) * C_ + cbase) * HW_ + h * W_ + wf;
    #pragma unroll
    for (int qp = 0; qp < 4; ++qp) {
        #pragma unroll
        for (int c = 0; c < 4; ++c) {
            float lo, hi;
            unpack2(lo, hi, acc[qp][c]);
            ob[(2 * qp) * CHW_ + c * HW_]     = lo;
            ob[(2 * qp + 1) * CHW_ + c * HW_] = hi;
        }
    }
}

extern "C" void kernel_launch(void* const* d_in, const int* in_sizes, int n_in,
                              void* d_out, int out_size)
{
    const float* x    = (const float*)d_in[0];   // (2,32,128,64,64)
    const float* attn = (const float*)d_in[1];   // (4,2,32,32,16,16)
    float* out        = (float*)d_out;           // (2,32,128,64,64)

    dim3 grid(T_ / TQ /*4 q-chunks*/, W_ / 32 /*2 w-chunks*/, B_ * G_ * H_ /*512*/);
    temporal_agg_kernel<<<grid, 256>>>(x, attn, out);
}